// round 1
// baseline (speedup 1.0000x reference)
#include <cuda_runtime.h>
#include <math.h>

#define N_NODES 50000
#define F_IN    256
#define F_OUT   128
#define ALPHA   0.2f

// Scratch (static __device__ arrays: allocation-free per harness rules)
__device__ float g_h[N_NODES * F_OUT];       // h = x @ W
__device__ float g_hp[N_NODES * F_OUT];      // h_prime accumulator
__device__ float g_rowsum[N_NODES];          // e_rowsum accumulator
__device__ float g_lin_s[N_NODES];           // h[i] . asum[:F_OUT]
__device__ float g_lin_d[N_NODES];           // h[i] . asum[F_OUT:]
__device__ float g_asum[2 * F_OUT];          // a.sum(axis=0)

// ---------------------------------------------------------------------------
// asum[c] = sum_r a[r][c],  a is [2F, 2F] row-major, 2F = 256
// ---------------------------------------------------------------------------
__global__ void asum_kernel(const float* __restrict__ a) {
    int c = threadIdx.x;  // 256 threads
    float s = 0.f;
    #pragma unroll 8
    for (int r = 0; r < 2 * F_OUT; r++)
        s += a[r * (2 * F_OUT) + c];
    g_asum[c] = s;
}

// ---------------------------------------------------------------------------
// Zero accumulators
// ---------------------------------------------------------------------------
__global__ void zero_kernel() {
    int i = blockIdx.x * blockDim.x + threadIdx.x;
    if (i < N_NODES * F_OUT) g_hp[i] = 0.f;
    if (i < N_NODES)         g_rowsum[i] = 0.f;
}

// ---------------------------------------------------------------------------
// fp32 GEMM: h[50000,128] = x[50000,256] @ W[256,128]
// Block: 256 threads computes 64 rows x 128 cols. Each thread: 8x4 outputs.
// Epilogue: per-node lin scalars  lin_s[i] = h[i].asum1, lin_d[i] = h[i].asum2
// ---------------------------------------------------------------------------
__global__ void gemm_kernel(const float* __restrict__ X,
                            const float* __restrict__ W) {
    __shared__ float As[16][68];    // [k][row], padded
    __shared__ float Bs[16][128];   // [k][col]
    __shared__ float red_s[256];
    __shared__ float red_d[256];

    const int block_row = blockIdx.x * 64;
    const int tid = threadIdx.x;
    const int tx = tid & 31;   // col group: cols tx*4 .. tx*4+3
    const int ty = tid >> 5;   // row group: rows ty*8 .. ty*8+7

    float acc[8][4];
    #pragma unroll
    for (int r = 0; r < 8; r++)
        #pragma unroll
        for (int c = 0; c < 4; c++) acc[r][c] = 0.f;

    const int arow = tid >> 2;  // 0..63
    const int akq  = tid & 3;   // 0..3

    for (int k0 = 0; k0 < F_IN; k0 += 16) {
        // Load A tile 64x16 (transposed into smem)
        int gr = block_row + arow;
        float4 av;
        if (gr < N_NODES)
            av = *reinterpret_cast<const float4*>(&X[(size_t)gr * F_IN + k0 + akq * 4]);
        else
            av = make_float4(0.f, 0.f, 0.f, 0.f);
        As[akq * 4 + 0][arow] = av.x;
        As[akq * 4 + 1][arow] = av.y;
        As[akq * 4 + 2][arow] = av.z;
        As[akq * 4 + 3][arow] = av.w;
        // Load B tile 16x128
        #pragma unroll
        for (int p = 0; p < 2; p++) {
            int ki = (tid >> 5) + p * 8;
            int c4 = (tid & 31) * 4;
            *reinterpret_cast<float4*>(&Bs[ki][c4]) =
                *reinterpret_cast<const float4*>(&W[(k0 + ki) * F_OUT + c4]);
        }
        __syncthreads();
        #pragma unroll
        for (int k = 0; k < 16; k++) {
            float a0[8];
            #pragma unroll
            for (int r = 0; r < 8; r++) a0[r] = As[k][ty * 8 + r];
            float4 b = *reinterpret_cast<float4*>(&Bs[k][tx * 4]);
            #pragma unroll
            for (int r = 0; r < 8; r++) {
                acc[r][0] += a0[r] * b.x;
                acc[r][1] += a0[r] * b.y;
                acc[r][2] += a0[r] * b.z;
                acc[r][3] += a0[r] * b.w;
            }
        }
        __syncthreads();
    }

    // Write h, and compute per-row lin scalars via per-thread partial dots.
    float4 a1 = *reinterpret_cast<const float4*>(&g_asum[tx * 4]);
    float4 a2 = *reinterpret_cast<const float4*>(&g_asum[F_OUT + tx * 4]);

    #pragma unroll
    for (int r = 0; r < 8; r++) {
        int gr = block_row + ty * 8 + r;
        float ps = acc[r][0] * a1.x + acc[r][1] * a1.y + acc[r][2] * a1.z + acc[r][3] * a1.w;
        float pd = acc[r][0] * a2.x + acc[r][1] * a2.y + acc[r][2] * a2.z + acc[r][3] * a2.w;
        // warp-reduce across the 32 col-threads (same warp shares ty)
        #pragma unroll
        for (int o = 16; o; o >>= 1) {
            ps += __shfl_xor_sync(0xFFFFFFFFu, ps, o);
            pd += __shfl_xor_sync(0xFFFFFFFFu, pd, o);
        }
        if (gr < N_NODES) {
            *reinterpret_cast<float4*>(&g_h[(size_t)gr * F_OUT + tx * 4]) =
                make_float4(acc[r][0], acc[r][1], acc[r][2], acc[r][3]);
            if (tx == 0) {
                g_lin_s[gr] = ps;
                g_lin_d[gr] = pd;
            }
        }
    }
    (void)red_s; (void)red_d;
}

// ---------------------------------------------------------------------------
// Edge kernel: one warp per edge.
//   conv = hs . hd  (warp reduction over 128 floats)
//   lin  = lin_s[src] + lin_d[dst]   (precomputed)
//   e    = exp(-leakyrelu(lin * sigmoid(conv)))
//   scatter: hp[src] += e * hd (vector RED), rowsum[src] += e
// ---------------------------------------------------------------------------
__global__ void edge_kernel(const int* __restrict__ ei, int E) {
    int warp = (blockIdx.x * blockDim.x + threadIdx.x) >> 5;
    int lane = threadIdx.x & 31;
    if (warp >= E) return;

    int src = ei[warp];
    int dst = ei[E + warp];

    float4 hs = *reinterpret_cast<const float4*>(&g_h[(size_t)src * F_OUT + lane * 4]);
    float4 hd = *reinterpret_cast<const float4*>(&g_h[(size_t)dst * F_OUT + lane * 4]);

    float conv = hs.x * hd.x + hs.y * hd.y + hs.z * hd.z + hs.w * hd.w;
    #pragma unroll
    for (int o = 16; o; o >>= 1)
        conv += __shfl_xor_sync(0xFFFFFFFFu, conv, o);

    float lin = g_lin_s[src] + g_lin_d[dst];
    float sig = 1.f / (1.f + expf(-conv));
    float z = lin * sig;
    float lr = (z >= 0.f) ? z : ALPHA * z;
    float e = expf(-lr);

    float* hp = &g_hp[(size_t)src * F_OUT + lane * 4];
    asm volatile("red.global.add.v4.f32 [%0], {%1,%2,%3,%4};"
                 :: "l"(hp), "f"(e * hd.x), "f"(e * hd.y), "f"(e * hd.z), "f"(e * hd.w)
                 : "memory");
    if (lane == 0)
        atomicAdd(&g_rowsum[src], e);
}

// ---------------------------------------------------------------------------
// Finalize: out = elu(hp / (rowsum + 1e-8))
// ---------------------------------------------------------------------------
__global__ void finalize_kernel(float* __restrict__ out) {
    int i = blockIdx.x * blockDim.x + threadIdx.x;
    if (i >= N_NODES * F_OUT) return;
    int node = i >> 7;  // /128
    float v = g_hp[i] / (g_rowsum[node] + 1e-8f);
    out[i] = (v > 0.f) ? v : expm1f(v);
}

// ---------------------------------------------------------------------------
extern "C" void kernel_launch(void* const* d_in, const int* in_sizes, int n_in,
                              void* d_out, int out_size) {
    const float* x  = (const float*)d_in[0];
    const int*   ei = (const int*)d_in[1];
    const float* W  = (const float*)d_in[2];
    const float* a  = (const float*)d_in[3];
    float* out = (float*)d_out;

    const int E = in_sizes[1] / 2;

    asum_kernel<<<1, 256>>>(a);
    zero_kernel<<<(N_NODES * F_OUT + 255) / 256, 256>>>();
    gemm_kernel<<<(N_NODES + 63) / 64, 256>>>(x, W);
    edge_kernel<<<(E + 7) / 8, 256>>>(ei, E);
    finalize_kernel<<<(N_NODES * F_OUT + 255) / 256, 256>>>(out);
}